// round 8
// baseline (speedup 1.0000x reference)
#include <cuda_runtime.h>
#include <math.h>
#include <stdint.h>

#define BB  4
#define TT  1024
#define EE  512
#define HH  8
#define EHD (EE*HH)   // 4096
#define BT  (BB*TT)   // 4096

// Scratch (device globals: allocation-free rule). All tf32-rounded fp32.
__device__ float g_X  [(size_t)BT*EE];          // rounded x
__device__ float g_W3 [(size_t)3*EHD*EE];       // rounded s*wq | s*wk | wv
__device__ float g_WU [(size_t)EE*EHD];         // rounded w_u
__device__ float g_QKV[(size_t)3*BT*EHD];       // rounded Q | K | V
__device__ float g_S  [(size_t)BB*HH*TT*TT];    // scores (fp32) -> P (rounded)
__device__ float g_A  [(size_t)BT*EHD];         // rounded attn out

// ---------------- helpers ---------------------------------------------------
__device__ __forceinline__ uint32_t smem_u32(const void* p) {
    uint32_t a;
    asm("{ .reg .u64 t; cvta.to.shared.u64 t, %1; cvt.u32.u64 %0, t; }"
        : "=r"(a) : "l"(p));
    return a;
}
__device__ __forceinline__ void cp16(uint32_t dst, const void* src) {
    asm volatile("cp.async.cg.shared.global [%0], [%1], 16;"
                 :: "r"(dst), "l"(src) : "memory");
}
__device__ __forceinline__ float tf32r(float f) {
    uint32_t r;
    asm("cvt.rna.tf32.f32 %0, %1;" : "=r"(r) : "f"(f));
    return __uint_as_float(r);
}
__device__ __forceinline__ void mma_tf32(float* c, const uint32_t* a,
                                         const uint32_t* b) {
    asm volatile(
        "mma.sync.aligned.m16n8k8.row.col.f32.tf32.tf32.f32 "
        "{%0,%1,%2,%3}, {%4,%5,%6,%7}, {%8,%9}, {%0,%1,%2,%3};"
        : "+f"(c[0]), "+f"(c[1]), "+f"(c[2]), "+f"(c[3])
        : "r"(a[0]), "r"(a[1]), "r"(a[2]), "r"(a[3]),
          "r"(b[0]), "r"(b[1]));
}

// SMEM geometry (fp32 words)
#define A_LD   36
#define BN_LD  36
#define BK_LDW 136
#define A_WORDS   (128*A_LD)
#define B_WORDS   4608
#define STAGE_W   (A_WORDS + B_WORDS)
#define SMSZ      (2*STAGE_W*4)       // 73728 B

// ---------------------------------------------------------------------------
// TF32 HMMA GEMM, 128x128 tile, BK=32, 8 warps (4x2), 32x64 per warp.
// Operands MUST be pre-rounded to tf32. BNT=1: B is [N,K]; BNT=0: [K,N].
// z -> (zo=z>>3, zi=z&7) strided batching. causal: skip bn>bm tiles.
// kclip: Keff=min(K,bm+128). rndC: round stores to tf32. redC: atomicAdd out.
// ---------------------------------------------------------------------------
template<int BNT>
__global__ __launch_bounds__(256) void gemm_tf32(
    int K,
    const float* __restrict__ A, int lda, size_t sAo, size_t sAi,
    const float* __restrict__ Bm, int ldb, size_t sBo, size_t sBi,
    float* __restrict__ C, int ldc, size_t sCo, size_t sCi,
    int causal, int kclip, int rndC, int redC)
{
    const int bm = blockIdx.y * 128, bn = blockIdx.x * 128;
    if (causal && bn > bm) return;

    const size_t zo = blockIdx.z >> 3, zi = blockIdx.z & 7;
    A  += zo * sAo + zi * sAi;
    Bm += zo * sBo + zi * sBi;
    C  += zo * sCo + zi * sCi;

    extern __shared__ float sm[];
    const uint32_t sbase = smem_u32(sm);

    const int tid  = threadIdx.x;
    const int wid  = tid >> 5, lane = tid & 31;
    const int wm   = wid >> 1, wn = wid & 1;
    const int arow = wm * 32;
    const int bcol = wn * 64;
    const int lg   = lane >> 2, lt = lane & 3;

    const int Keff = kclip ? min(K, bm + 128) : K;
    const int nch  = Keff >> 5;

    float acc[2][8][4];
#pragma unroll
    for (int mt = 0; mt < 2; mt++)
#pragma unroll
        for (int nt = 0; nt < 8; nt++)
#pragma unroll
            for (int i = 0; i < 4; i++) acc[mt][nt][i] = 0.f;

    auto prefetch = [&](int c) {
        const int k0  = c << 5;
        const uint32_t sA = sbase + (uint32_t)((c & 1) * STAGE_W) * 4;
        const uint32_t sB = sA + A_WORDS * 4;
#pragma unroll
        for (int i = 0; i < 4; i++) {
            const int e = tid + i * 256;
            const int r = e >> 3, cw = (e & 7) * 4;
            cp16(sA + (r * A_LD + cw) * 4,
                 A + (size_t)(bm + r) * lda + k0 + cw);
        }
        if (BNT) {
#pragma unroll
            for (int i = 0; i < 4; i++) {
                const int e = tid + i * 256;
                const int r = e >> 3, cw = (e & 7) * 4;
                cp16(sB + (r * BN_LD + cw) * 4,
                     Bm + (size_t)(bn + r) * ldb + k0 + cw);
            }
        } else {
#pragma unroll
            for (int i = 0; i < 4; i++) {
                const int e = tid + i * 256;
                const int r = e >> 5, cw = (e & 31) * 4;
                cp16(sB + (r * BK_LDW + cw) * 4,
                     Bm + (size_t)(k0 + r) * ldb + bn + cw);
            }
        }
        asm volatile("cp.async.commit_group;" ::: "memory");
    };

    prefetch(0);

    for (int c = 0; c < nch; c++) {
        asm volatile("cp.async.wait_group 0;" ::: "memory");
        __syncthreads();
        if (c + 1 < nch) prefetch(c + 1);

        const float* As = sm + (c & 1) * STAGE_W;
        const float* Bs = As + A_WORDS;
        const uint32_t* Au = (const uint32_t*)As;
        const uint32_t* Bu = (const uint32_t*)Bs;

#pragma unroll
        for (int ks = 0; ks < 4; ks++) {
            const int kf = ks * 8 + lt;
            uint32_t a[2][4], b[8][2];
#pragma unroll
            for (int mt = 0; mt < 2; mt++) {
                const int m = arow + mt * 16 + lg;
                a[mt][0] = Au[m * A_LD + kf];
                a[mt][1] = Au[(m + 8) * A_LD + kf];
                a[mt][2] = Au[m * A_LD + kf + 4];
                a[mt][3] = Au[(m + 8) * A_LD + kf + 4];
            }
#pragma unroll
            for (int nt = 0; nt < 8; nt++) {
                const int n = bcol + nt * 8 + lg;
                if (BNT) {
                    b[nt][0] = Bu[n * BN_LD + kf];
                    b[nt][1] = Bu[n * BN_LD + kf + 4];
                } else {
                    b[nt][0] = Bu[kf * BK_LDW + n];
                    b[nt][1] = Bu[(kf + 4) * BK_LDW + n];
                }
            }
#pragma unroll
            for (int mt = 0; mt < 2; mt++)
#pragma unroll
                for (int nt = 0; nt < 8; nt++)
                    mma_tf32(acc[mt][nt], a[mt], b[nt]);
        }
    }

    // ---- epilogue ----
#pragma unroll
    for (int mt = 0; mt < 2; mt++) {
#pragma unroll
        for (int nt = 0; nt < 8; nt++) {
            const int gn = bn + bcol + nt * 8 + 2 * lt;
            const int r0 = bm + arow + mt * 16 + lg;
            if (redC) {
                atomicAdd(&C[(size_t)r0 * ldc + gn],       acc[mt][nt][0]);
                atomicAdd(&C[(size_t)r0 * ldc + gn + 1],   acc[mt][nt][1]);
                atomicAdd(&C[(size_t)(r0+8) * ldc + gn],   acc[mt][nt][2]);
                atomicAdd(&C[(size_t)(r0+8) * ldc + gn+1], acc[mt][nt][3]);
            } else {
                float2 v0, v1;
                v0.x = acc[mt][nt][0]; v0.y = acc[mt][nt][1];
                v1.x = acc[mt][nt][2]; v1.y = acc[mt][nt][3];
                if (rndC) {
                    v0.x = tf32r(v0.x); v0.y = tf32r(v0.y);
                    v1.x = tf32r(v1.x); v1.y = tf32r(v1.y);
                }
                *(float2*)&C[(size_t)r0 * ldc + gn]       = v0;
                *(float2*)&C[(size_t)(r0 + 8) * ldc + gn] = v1;
            }
        }
    }
}

// ---------------- pre-round fp32 -> tf32 (optionally scaled) ----------------
__global__ __launch_bounds__(256) void round_tf32(
    const float4* __restrict__ src, float4* __restrict__ dst, float scale, int n4)
{
    const int i = blockIdx.x * 256 + threadIdx.x;
    if (i >= n4) return;
    float4 v = src[i];
    v.x = tf32r(v.x * scale); v.y = tf32r(v.y * scale);
    v.z = tf32r(v.z * scale); v.w = tf32r(v.w * scale);
    dst[i] = v;
}

// ---------------- out = broadcast bias (before split-K atomics) -------------
__global__ __launch_bounds__(256) void init_out(
    float* __restrict__ out, const float* __restrict__ bias)
{
    const int i = blockIdx.x * 256 + threadIdx.x;  // 2M elements
    out[i] = bias[i & (EE - 1)];
}

// ---------------- causal softmax; emits tf32-rounded P in place -------------
__global__ __launch_bounds__(256) void softmax_causal(float* __restrict__ S)
{
    const int row = blockIdx.x;
    const int q   = row & (TT - 1);
    const int len = q + 1;
    float* Sr = S + (size_t)row * TT;

    __shared__ float sh[8];
    const int tid = threadIdx.x;

    float m = -1e30f;
    for (int i = tid; i < len; i += 256) m = fmaxf(m, Sr[i]);
#pragma unroll
    for (int o = 16; o > 0; o >>= 1) m = fmaxf(m, __shfl_xor_sync(0xffffffffu, m, o));
    if ((tid & 31) == 0) sh[tid >> 5] = m;
    __syncthreads();
    m = fmaxf(fmaxf(fmaxf(sh[0], sh[1]), fmaxf(sh[2], sh[3])),
              fmaxf(fmaxf(sh[4], sh[5]), fmaxf(sh[6], sh[7])));
    __syncthreads();

    float s = 0.f;
    for (int i = tid; i < len; i += 256) {
        float e = __expf(Sr[i] - m);
        Sr[i] = e;
        s += e;
    }
#pragma unroll
    for (int o = 16; o > 0; o >>= 1) s += __shfl_xor_sync(0xffffffffu, s, o);
    if ((tid & 31) == 0) sh[tid >> 5] = s;
    __syncthreads();
    s = sh[0]+sh[1]+sh[2]+sh[3]+sh[4]+sh[5]+sh[6]+sh[7];
    const float inv = 1.0f / s;

    for (int i = tid; i < len; i += 256) Sr[i] = tf32r(Sr[i] * inv);
    for (int i = len + tid; i < TT; i += 256) Sr[i] = 0.f;
}

// ---------------------------------------------------------------------------
extern "C" void kernel_launch(void* const* d_in, const int* in_sizes, int n_in,
                              void* d_out, int out_size)
{
    const float* x   = (const float*)d_in[0];
    const float* w_k = (const float*)d_in[1];
    const float* w_q = (const float*)d_in[2];
    const float* w_v = (const float*)d_in[3];
    const float* w_u = (const float*)d_in[4];
    const float* b_u = (const float*)d_in[5];
    float* out = (float*)d_out;

    void *pX, *pW3, *pWU, *pQKV, *pS, *pA;
    cudaGetSymbolAddress(&pX,   g_X);
    cudaGetSymbolAddress(&pW3,  g_W3);
    cudaGetSymbolAddress(&pWU,  g_WU);
    cudaGetSymbolAddress(&pQKV, g_QKV);
    cudaGetSymbolAddress(&pS,   g_S);
    cudaGetSymbolAddress(&pA,   g_A);
    float* X   = (float*)pX;
    float* W3  = (float*)pW3;
    float* WU  = (float*)pWU;
    float* QKV = (float*)pQKV;
    float* Sc  = (float*)pS;
    float* Ab  = (float*)pA;

    float* Qp = QKV;
    float* Kp = QKV + (size_t)BT * EHD;
    float* Vp = QKV + (size_t)2 * BT * EHD;

    static int init = 0;
    if (!init) {
        cudaFuncSetAttribute(gemm_tf32<1>,
            cudaFuncAttributeMaxDynamicSharedMemorySize, SMSZ);
        cudaFuncSetAttribute(gemm_tf32<0>,
            cudaFuncAttributeMaxDynamicSharedMemorySize, SMSZ);
        init = 1;
    }

    const float s = 0.21022410381342864f;  // 512^(-1/4), folded into wq/wk
    const dim3 blk(256);
    const size_t z = 0;
    const size_t WPL = (size_t)EHD * EE;   // weight plane stride

    // 0) pre-round everything to tf32 (scale folded into wq, wk)
    const int n4 = (BT * EE) / 4;
    const int cb = (n4 + 255) / 256;
    round_tf32<<<cb, 256>>>((const float4*)x,   (float4*)X,            1.f, n4);
    round_tf32<<<cb, 256>>>((const float4*)w_q, (float4*)(W3),         s,   n4);
    round_tf32<<<cb, 256>>>((const float4*)w_k, (float4*)(W3 + WPL),   s,   n4);
    round_tf32<<<cb, 256>>>((const float4*)w_v, (float4*)(W3 + 2*WPL), 1.f, n4);
    round_tf32<<<cb, 256>>>((const float4*)w_u, (float4*)WU,           1.f, n4);
    init_out<<<(BT * EE) / 256, 256>>>(out, b_u);

    // 1) fused QKV projections: z selects weight/output plane (NT)
    gemm_tf32<1><<<dim3(32, 32, 3), blk, SMSZ>>>(EE,
        X,  EE,  z, z,
        W3, EE,  z, WPL,
        QKV, EHD, z, (size_t)BT * EHD,
        0, 0, 1, 0);

    // 2) scores: per (b,h) S = Q @ K^T, causal tile skip (NT)
    gemm_tf32<1><<<dim3(8, 8, 32), blk, SMSZ>>>(EE,
        Qp, EHD, (size_t)TT*EHD, (size_t)EE,
        Kp, EHD, (size_t)TT*EHD, (size_t)EE,
        Sc, TT,  (size_t)HH*TT*TT, (size_t)TT*TT,
        1, 0, 0, 0);

    // 3) causal softmax (rounds P to tf32 in place)
    softmax_causal<<<BB*HH*TT, 256>>>(Sc);

    // 4) PV: per (b,h) O = P @ V  (NN, K clipped), output rounded
    gemm_tf32<0><<<dim3(4, 8, 32), blk, SMSZ>>>(TT,
        Sc, TT,  (size_t)HH*TT*TT, (size_t)TT*TT,
        Vp, EHD, (size_t)TT*EHD,   (size_t)EE,
        Ab, EHD, (size_t)TT*EHD,   (size_t)EE,
        0, 1, 1, 0);

    // 5) unify: out += Ab @ w_u^T, split-K=2 via z, atomic epilogue (NT)
    gemm_tf32<1><<<dim3(4, 32, 2), blk, SMSZ>>>(EHD / 2,
        Ab, EHD, z, (size_t)(EHD / 2),
        WU, EHD, z, (size_t)(EHD / 2),
        out, EE, z, z,
        0, 0, 0, 1);
}

// round 9
// speedup vs baseline: 1.1137x; 1.1137x over previous
#include <cuda_runtime.h>
#include <math.h>
#include <stdint.h>

#define BB  4
#define TT  1024
#define EE  512
#define HH  8
#define EHD (EE*HH)   // 4096
#define BT  (BB*TT)   // 4096

// Scratch (device globals: allocation-free rule)
__device__ float g_WU [(size_t)EE*EHD];         // tf32-rounded w_u
__device__ float g_QKV[(size_t)3*BT*EHD];       // tf32-rounded Q | K | V
__device__ float g_S  [(size_t)BB*HH*TT*TT];    // scores -> P (tf32-rounded)
__device__ float g_A  [(size_t)BT*EHD];         // tf32-rounded attn out

// ---------------- helpers ---------------------------------------------------
__device__ __forceinline__ uint32_t smem_u32(const void* p) {
    uint32_t a;
    asm("{ .reg .u64 t; cvta.to.shared.u64 t, %1; cvt.u32.u64 %0, t; }"
        : "=r"(a) : "l"(p));
    return a;
}
__device__ __forceinline__ void cp16(uint32_t dst, const void* src) {
    asm volatile("cp.async.cg.shared.global [%0], [%1], 16;"
                 :: "r"(dst), "l"(src) : "memory");
}
__device__ __forceinline__ uint32_t tf32b(float f) {
    uint32_t r;
    asm("cvt.rna.tf32.f32 %0, %1;" : "=r"(r) : "f"(f));
    return r;
}
__device__ __forceinline__ float tf32r(float f) {
    return __uint_as_float(tf32b(f));
}
__device__ __forceinline__ void mma_tf32(float* c, const uint32_t* a,
                                         const uint32_t* b) {
    asm volatile(
        "mma.sync.aligned.m16n8k8.row.col.f32.tf32.tf32.f32 "
        "{%0,%1,%2,%3}, {%4,%5,%6,%7}, {%8,%9}, {%0,%1,%2,%3};"
        : "+f"(c[0]), "+f"(c[1]), "+f"(c[2]), "+f"(c[3])
        : "r"(a[0]), "r"(a[1]), "r"(a[2]), "r"(a[3]),
          "r"(b[0]), "r"(b[1]));
}

// SMEM geometry (fp32 words)
#define A_LD   36
#define BN_LD  36
#define BK_LDW 136
#define A_WORDS   (128*A_LD)
#define B_WORDS   4608
#define STAGE_W   (A_WORDS + B_WORDS)
#define SMSZ      (2*STAGE_W*4)       // 73728 B

// ---------------------------------------------------------------------------
// TF32 HMMA GEMM, 128x128 tile, BK=32, 8 warps (4x2), 32x64 per warp.
// BNT=1: B is [N,K] (NT); BNT=0: [K,N] (NN).
// CVT=1: round fragments to tf32 in-loop (raw fp32 operands).
// CVT=0: operands pre-rounded; fragments used as raw bits.
// fuse (QKV mode): B selected from {Bm,B1,B2} by zi, C += zi*sCi,
//                  epilogue scale applied to zi<2 planes only.
// causal: skip bn>bm tiles. kclip: Keff=min(K,bm+128).
// rndC: round stores to tf32. redC: atomicAdd into C (split-K).
// ---------------------------------------------------------------------------
template<int BNT, int CVT>
__global__ __launch_bounds__(256) void gemm_tf32(
    int K,
    const float* __restrict__ A, int lda, size_t sAo, size_t sAi,
    const float* __restrict__ Bm, int ldb, size_t sBo, size_t sBi,
    const float* __restrict__ B1, const float* __restrict__ B2,
    float* __restrict__ C, int ldc, size_t sCo, size_t sCi,
    int fuse, float scale,
    int causal, int kclip, int rndC, int redC)
{
    const int bm = blockIdx.y * 128, bn = blockIdx.x * 128;
    if (causal && bn > bm) return;

    const size_t zo = blockIdx.z >> 3, zi = blockIdx.z & 7;
    if (fuse) {
        Bm = (zi == 0) ? Bm : (zi == 1) ? B1 : B2;
        C += zi * sCi;
    } else {
        A  += zo * sAo + zi * sAi;
        Bm += zo * sBo + zi * sBi;
        C  += zo * sCo + zi * sCi;
    }

    extern __shared__ float sm[];
    const uint32_t sbase = smem_u32(sm);

    const int tid  = threadIdx.x;
    const int wid  = tid >> 5, lane = tid & 31;
    const int wm   = wid >> 1, wn = wid & 1;
    const int arow = wm * 32;
    const int bcol = wn * 64;
    const int lg   = lane >> 2, lt = lane & 3;

    const int Keff = kclip ? min(K, bm + 128) : K;
    const int nch  = Keff >> 5;

    float acc[2][8][4];
#pragma unroll
    for (int mt = 0; mt < 2; mt++)
#pragma unroll
        for (int nt = 0; nt < 8; nt++)
#pragma unroll
            for (int i = 0; i < 4; i++) acc[mt][nt][i] = 0.f;

    auto prefetch = [&](int c) {
        const int k0  = c << 5;
        const uint32_t sA = sbase + (uint32_t)((c & 1) * STAGE_W) * 4;
        const uint32_t sB = sA + A_WORDS * 4;
#pragma unroll
        for (int i = 0; i < 4; i++) {
            const int e = tid + i * 256;
            const int r = e >> 3, cw = (e & 7) * 4;
            cp16(sA + (r * A_LD + cw) * 4,
                 A + (size_t)(bm + r) * lda + k0 + cw);
        }
        if (BNT) {
#pragma unroll
            for (int i = 0; i < 4; i++) {
                const int e = tid + i * 256;
                const int r = e >> 3, cw = (e & 7) * 4;
                cp16(sB + (r * BN_LD + cw) * 4,
                     Bm + (size_t)(bn + r) * ldb + k0 + cw);
            }
        } else {
#pragma unroll
            for (int i = 0; i < 4; i++) {
                const int e = tid + i * 256;
                const int r = e >> 5, cw = (e & 31) * 4;
                cp16(sB + (r * BK_LDW + cw) * 4,
                     Bm + (size_t)(k0 + r) * ldb + bn + cw);
            }
        }
        asm volatile("cp.async.commit_group;" ::: "memory");
    };

    prefetch(0);

    for (int c = 0; c < nch; c++) {
        asm volatile("cp.async.wait_group 0;" ::: "memory");
        __syncthreads();
        if (c + 1 < nch) prefetch(c + 1);

        const float* As = sm + (c & 1) * STAGE_W;
        const float* Bs = As + A_WORDS;
        const uint32_t* Au = (const uint32_t*)As;
        const uint32_t* Bu = (const uint32_t*)Bs;

#pragma unroll
        for (int ks = 0; ks < 4; ks++) {
            const int kf = ks * 8 + lt;
            uint32_t a[2][4], b[8][2];
#pragma unroll
            for (int mt = 0; mt < 2; mt++) {
                const int m = arow + mt * 16 + lg;
                if (CVT) {
                    a[mt][0] = tf32b(As[m * A_LD + kf]);
                    a[mt][1] = tf32b(As[(m + 8) * A_LD + kf]);
                    a[mt][2] = tf32b(As[m * A_LD + kf + 4]);
                    a[mt][3] = tf32b(As[(m + 8) * A_LD + kf + 4]);
                } else {
                    a[mt][0] = Au[m * A_LD + kf];
                    a[mt][1] = Au[(m + 8) * A_LD + kf];
                    a[mt][2] = Au[m * A_LD + kf + 4];
                    a[mt][3] = Au[(m + 8) * A_LD + kf + 4];
                }
            }
#pragma unroll
            for (int nt = 0; nt < 8; nt++) {
                const int n = bcol + nt * 8 + lg;
                if (BNT) {
                    if (CVT) {
                        b[nt][0] = tf32b(Bs[n * BN_LD + kf]);
                        b[nt][1] = tf32b(Bs[n * BN_LD + kf + 4]);
                    } else {
                        b[nt][0] = Bu[n * BN_LD + kf];
                        b[nt][1] = Bu[n * BN_LD + kf + 4];
                    }
                } else {
                    if (CVT) {
                        b[nt][0] = tf32b(Bs[kf * BK_LDW + n]);
                        b[nt][1] = tf32b(Bs[(kf + 4) * BK_LDW + n]);
                    } else {
                        b[nt][0] = Bu[kf * BK_LDW + n];
                        b[nt][1] = Bu[(kf + 4) * BK_LDW + n];
                    }
                }
            }
#pragma unroll
            for (int mt = 0; mt < 2; mt++)
#pragma unroll
                for (int nt = 0; nt < 8; nt++)
                    mma_tf32(acc[mt][nt], a[mt], b[nt]);
        }
    }

    // ---- epilogue ----
    const float sc = fuse ? ((zi < 2) ? scale : 1.f) : scale;
#pragma unroll
    for (int mt = 0; mt < 2; mt++) {
#pragma unroll
        for (int nt = 0; nt < 8; nt++) {
            const int gn = bn + bcol + nt * 8 + 2 * lt;
            const int r0 = bm + arow + mt * 16 + lg;
            if (redC) {
                atomicAdd(&C[(size_t)r0 * ldc + gn],       acc[mt][nt][0]);
                atomicAdd(&C[(size_t)r0 * ldc + gn + 1],   acc[mt][nt][1]);
                atomicAdd(&C[(size_t)(r0+8) * ldc + gn],   acc[mt][nt][2]);
                atomicAdd(&C[(size_t)(r0+8) * ldc + gn+1], acc[mt][nt][3]);
            } else {
                float2 v0, v1;
                v0.x = acc[mt][nt][0] * sc; v0.y = acc[mt][nt][1] * sc;
                v1.x = acc[mt][nt][2] * sc; v1.y = acc[mt][nt][3] * sc;
                if (rndC) {
                    v0.x = tf32r(v0.x); v0.y = tf32r(v0.y);
                    v1.x = tf32r(v1.x); v1.y = tf32r(v1.y);
                }
                *(float2*)&C[(size_t)r0 * ldc + gn]       = v0;
                *(float2*)&C[(size_t)(r0 + 8) * ldc + gn] = v1;
            }
        }
    }
}

// ---------------- pre-round fp32 -> tf32 ------------------------------------
__global__ __launch_bounds__(256) void round_tf32(
    const float4* __restrict__ src, float4* __restrict__ dst, int n4)
{
    const int i = blockIdx.x * 256 + threadIdx.x;
    if (i >= n4) return;
    float4 v = src[i];
    v.x = tf32r(v.x); v.y = tf32r(v.y);
    v.z = tf32r(v.z); v.w = tf32r(v.w);
    dst[i] = v;
}

// ---------------- out = broadcast bias (before split-K atomics) -------------
__global__ __launch_bounds__(256) void init_out(
    float* __restrict__ out, const float* __restrict__ bias)
{
    const int i = blockIdx.x * 256 + threadIdx.x;
    out[i] = bias[i & (EE - 1)];
}

// ---------------- causal softmax; emits tf32-rounded P in place -------------
__global__ __launch_bounds__(256) void softmax_causal(float* __restrict__ S)
{
    const int row = blockIdx.x;
    const int q   = row & (TT - 1);
    const int len = q + 1;
    float* Sr = S + (size_t)row * TT;

    __shared__ float sh[8];
    const int tid = threadIdx.x;

    float m = -1e30f;
    for (int i = tid; i < len; i += 256) m = fmaxf(m, Sr[i]);
#pragma unroll
    for (int o = 16; o > 0; o >>= 1) m = fmaxf(m, __shfl_xor_sync(0xffffffffu, m, o));
    if ((tid & 31) == 0) sh[tid >> 5] = m;
    __syncthreads();
    m = fmaxf(fmaxf(fmaxf(sh[0], sh[1]), fmaxf(sh[2], sh[3])),
              fmaxf(fmaxf(sh[4], sh[5]), fmaxf(sh[6], sh[7])));
    __syncthreads();

    float s = 0.f;
    for (int i = tid; i < len; i += 256) {
        float e = __expf(Sr[i] - m);
        Sr[i] = e;
        s += e;
    }
#pragma unroll
    for (int o = 16; o > 0; o >>= 1) s += __shfl_xor_sync(0xffffffffu, s, o);
    if ((tid & 31) == 0) sh[tid >> 5] = s;
    __syncthreads();
    s = sh[0]+sh[1]+sh[2]+sh[3]+sh[4]+sh[5]+sh[6]+sh[7];
    const float inv = 1.0f / s;

    for (int i = tid; i < len; i += 256) Sr[i] = tf32r(Sr[i] * inv);
    for (int i = len + tid; i < TT; i += 256) Sr[i] = 0.f;
}

// ---------------------------------------------------------------------------
extern "C" void kernel_launch(void* const* d_in, const int* in_sizes, int n_in,
                              void* d_out, int out_size)
{
    const float* x   = (const float*)d_in[0];
    const float* w_k = (const float*)d_in[1];
    const float* w_q = (const float*)d_in[2];
    const float* w_v = (const float*)d_in[3];
    const float* w_u = (const float*)d_in[4];
    const float* b_u = (const float*)d_in[5];
    float* out = (float*)d_out;

    void *pWU, *pQKV, *pS, *pA;
    cudaGetSymbolAddress(&pWU,  g_WU);
    cudaGetSymbolAddress(&pQKV, g_QKV);
    cudaGetSymbolAddress(&pS,   g_S);
    cudaGetSymbolAddress(&pA,   g_A);
    float* WU  = (float*)pWU;
    float* QKV = (float*)pQKV;
    float* Sc  = (float*)pS;
    float* Ab  = (float*)pA;

    float* Qp = QKV;
    float* Kp = QKV + (size_t)BT * EHD;
    float* Vp = QKV + (size_t)2 * BT * EHD;

    static int init = 0;
    if (!init) {
        cudaFuncSetAttribute(gemm_tf32<1, 1>,
            cudaFuncAttributeMaxDynamicSharedMemorySize, SMSZ);
        cudaFuncSetAttribute(gemm_tf32<1, 0>,
            cudaFuncAttributeMaxDynamicSharedMemorySize, SMSZ);
        cudaFuncSetAttribute(gemm_tf32<0, 0>,
            cudaFuncAttributeMaxDynamicSharedMemorySize, SMSZ);
        init = 1;
    }

    const float s = 0.21022410381342864f;  // 512^(-1/4), applied to Q,K planes
    const dim3 blk(256);
    const size_t z = 0;

    // 0) round w_u (K=4096 consumer justifies it); bias-init out for split-K
    const int n4 = (EE * EHD) / 4;
    round_tf32<<<(n4 + 255) / 256, 256>>>((const float4*)w_u, (float4*)WU, n4);
    init_out<<<(BT * EE) / 256, 256>>>(out, b_u);

    // 1) fused QKV projections (CVT in-loop; rounded, scaled outputs)
    gemm_tf32<1, 1><<<dim3(32, 32, 3), blk, SMSZ>>>(EE,
        x,   EE, z, z,
        w_q, EE, z, z,  w_k, w_v,
        QKV, EHD, z, (size_t)BT * EHD,
        1, s, 0, 0, 1, 0);

    // 2) scores: per (b,h) S = Q @ K^T, causal tile skip (NT, pre-rounded)
    gemm_tf32<1, 0><<<dim3(8, 8, 32), blk, SMSZ>>>(EE,
        Qp, EHD, (size_t)TT*EHD, (size_t)EE,
        Kp, EHD, (size_t)TT*EHD, (size_t)EE,  nullptr, nullptr,
        Sc, TT,  (size_t)HH*TT*TT, (size_t)TT*TT,
        0, 1.f, 1, 0, 0, 0);

    // 3) causal softmax (rounds P to tf32 in place)
    softmax_causal<<<BB*HH*TT, 256>>>(Sc);

    // 4) PV: per (b,h) O = P @ V  (NN, K clipped, pre-rounded), rounded out
    gemm_tf32<0, 0><<<dim3(4, 8, 32), blk, SMSZ>>>(TT,
        Sc, TT,  (size_t)HH*TT*TT, (size_t)TT*TT,
        Vp, EHD, (size_t)TT*EHD,   (size_t)EE,  nullptr, nullptr,
        Ab, EHD, (size_t)TT*EHD,   (size_t)EE,
        0, 1.f, 0, 1, 1, 0);

    // 5) unify: out += Ab @ WU^T, split-K=2 via zi, atomic epilogue (NT)
    gemm_tf32<1, 0><<<dim3(4, 32, 2), blk, SMSZ>>>(EHD / 2,
        Ab, EHD, z, (size_t)(EHD / 2),
        WU, EHD, z, (size_t)(EHD / 2),  nullptr, nullptr,
        out, EE, z, z,
        0, 1.f, 0, 0, 0, 1);
}

// round 13
// speedup vs baseline: 1.1939x; 1.0720x over previous
#include <cuda_runtime.h>
#include <math.h>
#include <stdint.h>

#define BB  4
#define TT  1024
#define EE  512
#define HH  8
#define EHD (EE*HH)   // 4096
#define BT  (BB*TT)   // 4096

// Scratch (device globals: allocation-free rule)
__device__ float g_WU [(size_t)EE*EHD];         // tf32-rounded w_u
__device__ float g_QKV[(size_t)3*BT*EHD];       // tf32-rounded Q | K | V
__device__ float g_S  [(size_t)BB*HH*TT*TT];    // E = exp(scores), tf32-rounded
__device__ float g_A  [(size_t)BT*EHD];         // tf32-rounded attn out
__device__ float g_RS [(size_t)BB*HH*TT];       // softmax row sums

// ---------------- helpers ---------------------------------------------------
__device__ __forceinline__ uint32_t smem_u32(const void* p) {
    uint32_t a;
    asm("{ .reg .u64 t; cvta.to.shared.u64 t, %1; cvt.u32.u64 %0, t; }"
        : "=r"(a) : "l"(p));
    return a;
}
__device__ __forceinline__ void cp16(uint32_t dst, const void* src) {
    asm volatile("cp.async.cg.shared.global [%0], [%1], 16;"
                 :: "r"(dst), "l"(src) : "memory");
}
__device__ __forceinline__ uint32_t tf32b(float f) {
    uint32_t r;
    asm("cvt.rna.tf32.f32 %0, %1;" : "=r"(r) : "f"(f));
    return r;
}
__device__ __forceinline__ float tf32r(float f) {
    return __uint_as_float(tf32b(f));
}
__device__ __forceinline__ void mma_tf32(float* c, const uint32_t* a,
                                         const uint32_t* b) {
    asm volatile(
        "mma.sync.aligned.m16n8k8.row.col.f32.tf32.tf32.f32 "
        "{%0,%1,%2,%3}, {%4,%5,%6,%7}, {%8,%9}, {%0,%1,%2,%3};"
        : "+f"(c[0]), "+f"(c[1]), "+f"(c[2]), "+f"(c[3])
        : "r"(a[0]), "r"(a[1]), "r"(a[2]), "r"(a[3]),
          "r"(b[0]), "r"(b[1]));
}

// SMEM geometry (fp32 words)
#define A_LD   36
#define BN_LD  36
#define BK_LDW 136
#define A_WORDS   (128*A_LD)
#define B_WORDS   4608
#define STAGE_W   (A_WORDS + B_WORDS)
#define SMSZ      (2*STAGE_W*4)       // 73728 B

// ---------------------------------------------------------------------------
// TF32 HMMA GEMM, 128x128 tile, BK=32, 8 warps (4x2), 32x64 per warp.
// BNT=1: B is [N,K] (NT); BNT=0: [K,N] (NN).
// CVT=1: round fragments to tf32 in-loop; CVT=0: operands pre-rounded.
// fuse (QKV): B from {Bm,B1,B2} by zi, C += zi*sCi, scale on zi<2 only.
// causal: skip bn>bm tiles. kclip: Keff=min(K,bm+128).
// epi: 0 = scale(+rndC) store;
//      1 = exp + causal mask + tf32 store + row-sum atomics into rsum;
//      2 = divide by rsum[row], tf32 store;
//      3 = atomicAdd into C (split-K).
// ---------------------------------------------------------------------------
template<int BNT, int CVT>
__global__ __launch_bounds__(256) void gemm_tf32(
    int K,
    const float* __restrict__ A, int lda, size_t sAo, size_t sAi,
    const float* __restrict__ Bm, int ldb, size_t sBo, size_t sBi,
    const float* __restrict__ B1, const float* __restrict__ B2,
    float* __restrict__ C, int ldc, size_t sCo, size_t sCi,
    int fuse, float scale, int causal, int kclip, int epi, int rndC,
    float* __restrict__ rsum)
{
    const int bm = blockIdx.y * 128, bn = blockIdx.x * 128;
    if (causal && bn > bm) return;

    const size_t zo = blockIdx.z >> 3, zi = blockIdx.z & 7;
    if (fuse) {
        Bm = (zi == 0) ? Bm : (zi == 1) ? B1 : B2;
        C += zi * sCi;
    } else {
        A  += zo * sAo + zi * sAi;
        Bm += zo * sBo + zi * sBi;
        C  += zo * sCo + zi * sCi;
    }
    if (rsum) rsum += (size_t)blockIdx.z * TT;

    extern __shared__ float sm[];
    const uint32_t sbase = smem_u32(sm);

    const int tid  = threadIdx.x;
    const int wid  = tid >> 5, lane = tid & 31;
    const int wm   = wid >> 1, wn = wid & 1;
    const int arow = wm * 32;
    const int bcol = wn * 64;
    const int lg   = lane >> 2, lt = lane & 3;

    const int Keff = kclip ? min(K, bm + 128) : K;
    const int nch  = Keff >> 5;

    float acc[2][8][4];
#pragma unroll
    for (int mt = 0; mt < 2; mt++)
#pragma unroll
        for (int nt = 0; nt < 8; nt++)
#pragma unroll
            for (int i = 0; i < 4; i++) acc[mt][nt][i] = 0.f;

    auto prefetch = [&](int c) {
        const int k0  = c << 5;
        const uint32_t sA = sbase + (uint32_t)((c & 1) * STAGE_W) * 4;
        const uint32_t sB = sA + A_WORDS * 4;
#pragma unroll
        for (int i = 0; i < 4; i++) {
            const int e = tid + i * 256;
            const int r = e >> 3, cw = (e & 7) * 4;
            cp16(sA + (r * A_LD + cw) * 4,
                 A + (size_t)(bm + r) * lda + k0 + cw);
        }
        if (BNT) {
#pragma unroll
            for (int i = 0; i < 4; i++) {
                const int e = tid + i * 256;
                const int r = e >> 3, cw = (e & 7) * 4;
                cp16(sB + (r * BN_LD + cw) * 4,
                     Bm + (size_t)(bn + r) * ldb + k0 + cw);
            }
        } else {
#pragma unroll
            for (int i = 0; i < 4; i++) {
                const int e = tid + i * 256;
                const int r = e >> 5, cw = (e & 31) * 4;
                cp16(sB + (r * BK_LDW + cw) * 4,
                     Bm + (size_t)(k0 + r) * ldb + bn + cw);
            }
        }
        asm volatile("cp.async.commit_group;" ::: "memory");
    };

    prefetch(0);

    for (int c = 0; c < nch; c++) {
        asm volatile("cp.async.wait_group 0;" ::: "memory");
        __syncthreads();
        if (c + 1 < nch) prefetch(c + 1);

        const float* As = sm + (c & 1) * STAGE_W;
        const float* Bs = As + A_WORDS;
        const uint32_t* Au = (const uint32_t*)As;
        const uint32_t* Bu = (const uint32_t*)Bs;

#pragma unroll
        for (int ks = 0; ks < 4; ks++) {
            const int kf = ks * 8 + lt;
            uint32_t a[2][4], b[8][2];
#pragma unroll
            for (int mt = 0; mt < 2; mt++) {
                const int m = arow + mt * 16 + lg;
                if (CVT) {
                    a[mt][0] = tf32b(As[m * A_LD + kf]);
                    a[mt][1] = tf32b(As[(m + 8) * A_LD + kf]);
                    a[mt][2] = tf32b(As[m * A_LD + kf + 4]);
                    a[mt][3] = tf32b(As[(m + 8) * A_LD + kf + 4]);
                } else {
                    a[mt][0] = Au[m * A_LD + kf];
                    a[mt][1] = Au[(m + 8) * A_LD + kf];
                    a[mt][2] = Au[m * A_LD + kf + 4];
                    a[mt][3] = Au[(m + 8) * A_LD + kf + 4];
                }
            }
#pragma unroll
            for (int nt = 0; nt < 8; nt++) {
                const int n = bcol + nt * 8 + lg;
                if (BNT) {
                    if (CVT) {
                        b[nt][0] = tf32b(Bs[n * BN_LD + kf]);
                        b[nt][1] = tf32b(Bs[n * BN_LD + kf + 4]);
                    } else {
                        b[nt][0] = Bu[n * BN_LD + kf];
                        b[nt][1] = Bu[n * BN_LD + kf + 4];
                    }
                } else {
                    if (CVT) {
                        b[nt][0] = tf32b(Bs[kf * BK_LDW + n]);
                        b[nt][1] = tf32b(Bs[(kf + 4) * BK_LDW + n]);
                    } else {
                        b[nt][0] = Bu[kf * BK_LDW + n];
                        b[nt][1] = Bu[(kf + 4) * BK_LDW + n];
                    }
                }
            }
#pragma unroll
            for (int mt = 0; mt < 2; mt++)
#pragma unroll
                for (int nt = 0; nt < 8; nt++)
                    mma_tf32(acc[mt][nt], a[mt], b[nt]);
        }
    }

    // ---- epilogue ----
    if (epi == 1) {
        // exp + causal mask + tf32 store + row-sum accumulation
        float rs[2][2] = {{0.f, 0.f}, {0.f, 0.f}};
#pragma unroll
        for (int mt = 0; mt < 2; mt++) {
            const int r0 = bm + arow + mt * 16 + lg;
#pragma unroll
            for (int nt = 0; nt < 8; nt++) {
                const int gn = bn + bcol + nt * 8 + 2 * lt;
                float e0 = (gn     <= r0)     ? __expf(acc[mt][nt][0]) : 0.f;
                float e1 = (gn + 1 <= r0)     ? __expf(acc[mt][nt][1]) : 0.f;
                float e2 = (gn     <= r0 + 8) ? __expf(acc[mt][nt][2]) : 0.f;
                float e3 = (gn + 1 <= r0 + 8) ? __expf(acc[mt][nt][3]) : 0.f;
                rs[mt][0] += e0 + e1;
                rs[mt][1] += e2 + e3;
                float2 v0, v1;
                v0.x = tf32r(e0); v0.y = tf32r(e1);
                v1.x = tf32r(e2); v1.y = tf32r(e3);
                *(float2*)&C[(size_t)r0 * ldc + gn]       = v0;
                *(float2*)&C[(size_t)(r0 + 8) * ldc + gn] = v1;
            }
        }
#pragma unroll
        for (int mt = 0; mt < 2; mt++)
#pragma unroll
            for (int h = 0; h < 2; h++) {
                float v = rs[mt][h];
                v += __shfl_xor_sync(0xffffffffu, v, 1);
                v += __shfl_xor_sync(0xffffffffu, v, 2);
                if (lt == 0)
                    atomicAdd(&rsum[bm + arow + mt * 16 + lg + h * 8], v);
            }
    } else if (epi == 2) {
        // divide by row sum, tf32 store
#pragma unroll
        for (int mt = 0; mt < 2; mt++) {
            const int r0 = bm + arow + mt * 16 + lg;
            const float i0 = 1.f / rsum[r0];
            const float i1 = 1.f / rsum[r0 + 8];
#pragma unroll
            for (int nt = 0; nt < 8; nt++) {
                const int gn = bn + bcol + nt * 8 + 2 * lt;
                float2 v0, v1;
                v0.x = tf32r(acc[mt][nt][0] * i0);
                v0.y = tf32r(acc[mt][nt][1] * i0);
                v1.x = tf32r(acc[mt][nt][2] * i1);
                v1.y = tf32r(acc[mt][nt][3] * i1);
                *(float2*)&C[(size_t)r0 * ldc + gn]       = v0;
                *(float2*)&C[(size_t)(r0 + 8) * ldc + gn] = v1;
            }
        }
    } else if (epi == 3) {
#pragma unroll
        for (int mt = 0; mt < 2; mt++) {
#pragma unroll
            for (int nt = 0; nt < 8; nt++) {
                const int gn = bn + bcol + nt * 8 + 2 * lt;
                const int r0 = bm + arow + mt * 16 + lg;
                atomicAdd(&C[(size_t)r0 * ldc + gn],       acc[mt][nt][0]);
                atomicAdd(&C[(size_t)r0 * ldc + gn + 1],   acc[mt][nt][1]);
                atomicAdd(&C[(size_t)(r0+8) * ldc + gn],   acc[mt][nt][2]);
                atomicAdd(&C[(size_t)(r0+8) * ldc + gn+1], acc[mt][nt][3]);
            }
        }
    } else {
        const float sc = fuse ? ((zi < 2) ? scale : 1.f) : scale;
#pragma unroll
        for (int mt = 0; mt < 2; mt++) {
#pragma unroll
            for (int nt = 0; nt < 8; nt++) {
                const int gn = bn + bcol + nt * 8 + 2 * lt;
                const int r0 = bm + arow + mt * 16 + lg;
                float2 v0, v1;
                v0.x = acc[mt][nt][0] * sc; v0.y = acc[mt][nt][1] * sc;
                v1.x = acc[mt][nt][2] * sc; v1.y = acc[mt][nt][3] * sc;
                if (rndC) {
                    v0.x = tf32r(v0.x); v0.y = tf32r(v0.y);
                    v1.x = tf32r(v1.x); v1.y = tf32r(v1.y);
                }
                *(float2*)&C[(size_t)r0 * ldc + gn]       = v0;
                *(float2*)&C[(size_t)(r0 + 8) * ldc + gn] = v1;
            }
        }
    }
}

// ---------------- pre-round fp32 -> tf32 ------------------------------------
__global__ __launch_bounds__(256) void round_tf32(
    const float4* __restrict__ src, float4* __restrict__ dst, int n4)
{
    const int i = blockIdx.x * 256 + threadIdx.x;
    if (i >= n4) return;
    float4 v = src[i];
    v.x = tf32r(v.x); v.y = tf32r(v.y);
    v.z = tf32r(v.z); v.w = tf32r(v.w);
    dst[i] = v;
}

// ---------------- out = broadcast bias; zero row sums -----------------------
__global__ __launch_bounds__(256) void init_out(
    float* __restrict__ out, const float* __restrict__ bias,
    float* __restrict__ rsum)
{
    const int i = blockIdx.x * 256 + threadIdx.x;
    out[i] = bias[i & (EE - 1)];
    if (i < BB * HH * TT) rsum[i] = 0.f;
}

// ---------------------------------------------------------------------------
extern "C" void kernel_launch(void* const* d_in, const int* in_sizes, int n_in,
                              void* d_out, int out_size)
{
    const float* x   = (const float*)d_in[0];
    const float* w_k = (const float*)d_in[1];
    const float* w_q = (const float*)d_in[2];
    const float* w_v = (const float*)d_in[3];
    const float* w_u = (const float*)d_in[4];
    const float* b_u = (const float*)d_in[5];
    float* out = (float*)d_out;

    void *pWU, *pQKV, *pS, *pA, *pRS;
    cudaGetSymbolAddress(&pWU,  g_WU);
    cudaGetSymbolAddress(&pQKV, g_QKV);
    cudaGetSymbolAddress(&pS,   g_S);
    cudaGetSymbolAddress(&pA,   g_A);
    cudaGetSymbolAddress(&pRS,  g_RS);
    float* WU  = (float*)pWU;
    float* QKV = (float*)pQKV;
    float* Sc  = (float*)pS;
    float* Ab  = (float*)pA;
    float* RS  = (float*)pRS;

    float* Qp = QKV;
    float* Kp = QKV + (size_t)BT * EHD;
    float* Vp = QKV + (size_t)2 * BT * EHD;

    static int init = 0;
    if (!init) {
        cudaFuncSetAttribute(gemm_tf32<1, 1>,
            cudaFuncAttributeMaxDynamicSharedMemorySize, SMSZ);
        cudaFuncSetAttribute(gemm_tf32<1, 0>,
            cudaFuncAttributeMaxDynamicSharedMemorySize, SMSZ);
        cudaFuncSetAttribute(gemm_tf32<0, 0>,
            cudaFuncAttributeMaxDynamicSharedMemorySize, SMSZ);
        init = 1;
    }

    const float s = 0.21022410381342864f;  // 512^(-1/4), applied to Q,K planes
    const dim3 blk(256);
    const size_t z = 0;

    // 0) round w_u; bias-init out (split-K target); zero row sums
    const int n4 = (EE * EHD) / 4;
    round_tf32<<<(n4 + 255) / 256, 256>>>((const float4*)w_u, (float4*)WU, n4);
    init_out<<<(BT * EE) / 256, 256>>>(out, b_u, RS);

    // 1) fused QKV projections (CVT in-loop; rounded, scaled outputs)
    gemm_tf32<1, 1><<<dim3(32, 32, 3), blk, SMSZ>>>(EE,
        x,   EE, z, z,
        w_q, EE, z, z,  w_k, w_v,
        QKV, EHD, z, (size_t)BT * EHD,
        1, s, 0, 0, 0, 1, nullptr);

    // 2) scores + fused exp/mask/row-sum: E = exp(Q @ K^T), causal tile skip
    gemm_tf32<1, 0><<<dim3(8, 8, 32), blk, SMSZ>>>(EE,
        Qp, EHD, (size_t)TT*EHD, (size_t)EE,
        Kp, EHD, (size_t)TT*EHD, (size_t)EE,  nullptr, nullptr,
        Sc, TT,  (size_t)HH*TT*TT, (size_t)TT*TT,
        0, 1.f, 1, 0, 1, 0, RS);

    // 3) PV: per (b,h) O = (E @ V) / rsum  (NN, K clipped), rounded out
    gemm_tf32<0, 0><<<dim3(4, 8, 32), blk, SMSZ>>>(TT,
        Sc, TT,  (size_t)HH*TT*TT, (size_t)TT*TT,
        Vp, EHD, (size_t)TT*EHD,   (size_t)EE,  nullptr, nullptr,
        Ab, EHD, (size_t)TT*EHD,   (size_t)EE,
        0, 1.f, 0, 1, 2, 0, RS);

    // 4) unify: out += Ab @ WU^T, split-K=2 via zi, atomic epilogue (NT)
    gemm_tf32<1, 0><<<dim3(4, 32, 2), blk, SMSZ>>>(EHD / 2,
        Ab, EHD, z, (size_t)(EHD / 2),
        WU, EHD, z, (size_t)(EHD / 2),  nullptr, nullptr,
        out, EE, z, z,
        0, 1.f, 0, 0, 3, 0, nullptr);
}